// round 2
// baseline (speedup 1.0000x reference)
#include <cuda_runtime.h>
#include <cuda_bf16.h>

// Problem constants (fixed shapes for this problem)
#define N_ROW  8192
#define N_COL  8192
#define RANK   256

// Scratch for row/col squared norms (no dynamic allocation allowed)
__device__ float g_x2[N_ROW];
__device__ float g_y2[N_COL];

// ---------------------------------------------------------------------------
// x2[i] = sum_k X[i][k]^2   (X is row-major [N_ROW, RANK], K contiguous)
// ---------------------------------------------------------------------------
__global__ void row_norms_kernel(const float* __restrict__ X) {
    int i = blockIdx.x * blockDim.x + threadIdx.x;
    if (i >= N_ROW) return;
    const float4* x = reinterpret_cast<const float4*>(X + (size_t)i * RANK);
    float s = 0.f;
#pragma unroll 16
    for (int k = 0; k < RANK / 4; ++k) {
        float4 v = x[k];
        s = fmaf(v.x, v.x, s);
        s = fmaf(v.y, v.y, s);
        s = fmaf(v.z, v.z, s);
        s = fmaf(v.w, v.w, s);
    }
    g_x2[i] = s;
}

// ---------------------------------------------------------------------------
// y2[j] = sum_k Y[k][j]^2   (Y is row-major [RANK, N_COL], N contiguous)
// ---------------------------------------------------------------------------
__global__ void col_norms_kernel(const float* __restrict__ Y) {
    int j = blockIdx.x * blockDim.x + threadIdx.x;
    if (j >= N_COL) return;
    float s = 0.f;
#pragma unroll 8
    for (int k = 0; k < RANK; ++k) {
        float v = Y[(size_t)k * N_COL + j];
        s = fmaf(v, v, s);
    }
    g_y2[j] = s;
}

// ---------------------------------------------------------------------------
// Fused SGEMM + epilogue:
//   cross = X @ Y
//   z     = beta - sqrt(max(x2[i] + y2[j] - 2*cross, 0))
//
// 128x128 block tile, BK=8, 256 threads, 8x8 outputs per thread arranged as
// 2x2 quads of float4 (rows {tr*4, tr*4+64}, cols {tc*4, tc*4+64}) so shared
// loads are conflict-free float4 and stores are float4.
// Double-buffered smem, one __syncthreads per K-tile.
// ---------------------------------------------------------------------------
__global__ __launch_bounds__(256, 2)
void l2_gemm_kernel(const float* __restrict__ X,
                    const float* __restrict__ Y,
                    const float* __restrict__ beta,
                    float* __restrict__ out) {
    __shared__ float As[2][8][128];   // [buf][k][m]  (transposed A tile)
    __shared__ float Bs[2][8][128];   // [buf][k][n]

    const int tid  = threadIdx.x;
    const int tr   = tid >> 4;        // 0..15  (row group)
    const int tc   = tid & 15;        // 0..15  (col group)
    const int brow = blockIdx.y * 128;
    const int bcol = blockIdx.x * 128;

    // Global-load assignments (one float4 per thread per tile, for A and B)
    const int a_row  = tid >> 1;          // 0..127
    const int a_col4 = (tid & 1) * 4;     // 0 or 4
    const int b_krow = tid >> 5;          // 0..7
    const int b_col4 = (tid & 31) * 4;    // 0..124

    const float* Aptr = X + (size_t)(brow + a_row) * RANK + a_col4;
    const float* Bptr = Y + (size_t)b_krow * N_COL + bcol + b_col4;

    float acc[8][8];
#pragma unroll
    for (int i = 0; i < 8; ++i)
#pragma unroll
        for (int j = 0; j < 8; ++j) acc[i][j] = 0.f;

    // --- preload tile 0 into buffer 0 ---
    {
        float4 av = *reinterpret_cast<const float4*>(Aptr);
        float4 bv = *reinterpret_cast<const float4*>(Bptr);
        As[0][a_col4 + 0][a_row] = av.x;
        As[0][a_col4 + 1][a_row] = av.y;
        As[0][a_col4 + 2][a_row] = av.z;
        As[0][a_col4 + 3][a_row] = av.w;
        *reinterpret_cast<float4*>(&Bs[0][b_krow][b_col4]) = bv;
    }
    __syncthreads();

    const int NKT = RANK / 8;  // 32 K-tiles
#pragma unroll 1
    for (int kt = 0; kt < NKT; ++kt) {
        const int cur = kt & 1;
        const int nxt = cur ^ 1;

        float4 av, bv;
        if (kt < NKT - 1) {
            av = *reinterpret_cast<const float4*>(Aptr + (kt + 1) * 8);
            bv = *reinterpret_cast<const float4*>(Bptr + (size_t)(kt + 1) * 8 * N_COL);
        }

#pragma unroll
        for (int k = 0; k < 8; ++k) {
            float a[8], b[8];
            *reinterpret_cast<float4*>(&a[0]) =
                *reinterpret_cast<const float4*>(&As[cur][k][tr * 4]);
            *reinterpret_cast<float4*>(&a[4]) =
                *reinterpret_cast<const float4*>(&As[cur][k][tr * 4 + 64]);
            *reinterpret_cast<float4*>(&b[0]) =
                *reinterpret_cast<const float4*>(&Bs[cur][k][tc * 4]);
            *reinterpret_cast<float4*>(&b[4]) =
                *reinterpret_cast<const float4*>(&Bs[cur][k][tc * 4 + 64]);
#pragma unroll
            for (int i = 0; i < 8; ++i)
#pragma unroll
                for (int j = 0; j < 8; ++j)
                    acc[i][j] = fmaf(a[i], b[j], acc[i][j]);
        }

        if (kt < NKT - 1) {
            As[nxt][a_col4 + 0][a_row] = av.x;
            As[nxt][a_col4 + 1][a_row] = av.y;
            As[nxt][a_col4 + 2][a_row] = av.z;
            As[nxt][a_col4 + 3][a_row] = av.w;
            *reinterpret_cast<float4*>(&Bs[nxt][b_krow][b_col4]) = bv;
            __syncthreads();
        }
    }

    // --- fused epilogue: z = beta - sqrt(max(x2 + y2 - 2*cross, 0)) ---
    const float beta_v = __ldg(beta);

    float xr[8], yc[8];
#pragma unroll
    for (int i = 0; i < 8; ++i) {
        int r = (i < 4) ? (tr * 4 + i) : (tr * 4 + 64 + (i - 4));
        xr[i] = g_x2[brow + r];
    }
#pragma unroll
    for (int j = 0; j < 8; ++j) {
        int c = (j < 4) ? (tc * 4 + j) : (tc * 4 + 64 + (j - 4));
        yc[j] = g_y2[bcol + c];
    }

#pragma unroll
    for (int i = 0; i < 8; ++i) {
        int r = (i < 4) ? (tr * 4 + i) : (tr * 4 + 64 + (i - 4));
        float* orow = out + (size_t)(brow + r) * N_COL + bcol;
        float z[8];
#pragma unroll
        for (int j = 0; j < 8; ++j) {
            float d2 = xr[i] + yc[j] - 2.f * acc[i][j];
            d2 = fmaxf(d2, 0.f);
            z[j] = beta_v - sqrtf(d2);
        }
        *reinterpret_cast<float4*>(orow + tc * 4)      = *reinterpret_cast<float4*>(&z[0]);
        *reinterpret_cast<float4*>(orow + tc * 4 + 64) = *reinterpret_cast<float4*>(&z[4]);
    }
}

// ---------------------------------------------------------------------------
extern "C" void kernel_launch(void* const* d_in, const int* in_sizes, int n_in,
                              void* d_out, int out_size) {
    const float* X    = (const float*)d_in[0];  // [8192, 256]
    const float* Y    = (const float*)d_in[1];  // [256, 8192]
    const float* beta = (const float*)d_in[2];  // [1]
    float* out        = (float*)d_out;          // [8192, 8192]

    row_norms_kernel<<<N_ROW / 256, 256>>>(X);
    col_norms_kernel<<<N_COL / 256, 256>>>(Y);

    dim3 grid(N_COL / 128, N_ROW / 128);
    l2_gemm_kernel<<<grid, 256>>>(X, Y, beta, out);
}

// round 4
// speedup vs baseline: 1.0023x; 1.0023x over previous
#include <cuda_runtime.h>
#include <cuda_bf16.h>

// Problem constants (fixed shapes for this problem)
#define N_ROW  8192
#define N_COL  8192
#define RANK   256

// Scratch for row/col squared norms (no dynamic allocation allowed)
__device__ float g_x2[N_ROW];
__device__ float g_y2[N_COL];

// ---------------------------------------------------------------------------
// x2[i] = sum_k X[i][k]^2   (X is row-major [N_ROW, RANK], K contiguous)
// ---------------------------------------------------------------------------
__global__ void row_norms_kernel(const float* __restrict__ X) {
    int i = blockIdx.x * blockDim.x + threadIdx.x;
    if (i >= N_ROW) return;
    const float4* x = reinterpret_cast<const float4*>(X + (size_t)i * RANK);
    float s = 0.f;
#pragma unroll 16
    for (int k = 0; k < RANK / 4; ++k) {
        float4 v = x[k];
        s = fmaf(v.x, v.x, s);
        s = fmaf(v.y, v.y, s);
        s = fmaf(v.z, v.z, s);
        s = fmaf(v.w, v.w, s);
    }
    g_x2[i] = s;
}

// ---------------------------------------------------------------------------
// y2[j] = sum_k Y[k][j]^2   (Y is row-major [RANK, N_COL], N contiguous)
// ---------------------------------------------------------------------------
__global__ void col_norms_kernel(const float* __restrict__ Y) {
    int j = blockIdx.x * blockDim.x + threadIdx.x;
    if (j >= N_COL) return;
    float s = 0.f;
#pragma unroll 8
    for (int k = 0; k < RANK; ++k) {
        float v = Y[(size_t)k * N_COL + j];
        s = fmaf(v, v, s);
    }
    g_y2[j] = s;
}

// ---------------------------------------------------------------------------
// Fused SGEMM + epilogue:
//   cross = X @ Y
//   z     = beta - sqrt(max(x2[i] + y2[j] - 2*cross, 0))
//
// 128x128 block tile, BK=8, 256 threads, 8x8 outputs per thread arranged as
// 2x2 quads of float4 (rows {tr*4, tr*4+64}, cols {tc*4, tc*4+64}) so shared
// loads are conflict-free float4 and stores are float4.
// Double-buffered smem, one __syncthreads per K-tile.
// ---------------------------------------------------------------------------
__global__ __launch_bounds__(256, 2)
void l2_gemm_kernel(const float* __restrict__ X,
                    const float* __restrict__ Y,
                    const float* __restrict__ beta,
                    float* __restrict__ out) {
    __shared__ float As[2][8][128];   // [buf][k][m]  (transposed A tile)
    __shared__ float Bs[2][8][128];   // [buf][k][n]

    const int tid  = threadIdx.x;
    const int tr   = tid >> 4;        // 0..15  (row group)
    const int tc   = tid & 15;        // 0..15  (col group)
    const int brow = blockIdx.y * 128;
    const int bcol = blockIdx.x * 128;

    // Global-load assignments (one float4 per thread per tile, for A and B)
    const int a_row  = tid >> 1;          // 0..127
    const int a_col4 = (tid & 1) * 4;     // 0 or 4
    const int b_krow = tid >> 5;          // 0..7
    const int b_col4 = (tid & 31) * 4;    // 0..124

    const float* Aptr = X + (size_t)(brow + a_row) * RANK + a_col4;
    const float* Bptr = Y + (size_t)b_krow * N_COL + bcol + b_col4;

    float acc[8][8];
#pragma unroll
    for (int i = 0; i < 8; ++i)
#pragma unroll
        for (int j = 0; j < 8; ++j) acc[i][j] = 0.f;

    // --- preload tile 0 into buffer 0 ---
    {
        float4 av = *reinterpret_cast<const float4*>(Aptr);
        float4 bv = *reinterpret_cast<const float4*>(Bptr);
        As[0][a_col4 + 0][a_row] = av.x;
        As[0][a_col4 + 1][a_row] = av.y;
        As[0][a_col4 + 2][a_row] = av.z;
        As[0][a_col4 + 3][a_row] = av.w;
        *reinterpret_cast<float4*>(&Bs[0][b_krow][b_col4]) = bv;
    }
    __syncthreads();

    const int NKT = RANK / 8;  // 32 K-tiles
#pragma unroll 1
    for (int kt = 0; kt < NKT; ++kt) {
        const int cur = kt & 1;
        const int nxt = cur ^ 1;

        float4 av, bv;
        if (kt < NKT - 1) {
            av = *reinterpret_cast<const float4*>(Aptr + (kt + 1) * 8);
            bv = *reinterpret_cast<const float4*>(Bptr + (size_t)(kt + 1) * 8 * N_COL);
        }

#pragma unroll
        for (int k = 0; k < 8; ++k) {
            float a[8], b[8];
            *reinterpret_cast<float4*>(&a[0]) =
                *reinterpret_cast<const float4*>(&As[cur][k][tr * 4]);
            *reinterpret_cast<float4*>(&a[4]) =
                *reinterpret_cast<const float4*>(&As[cur][k][tr * 4 + 64]);
            *reinterpret_cast<float4*>(&b[0]) =
                *reinterpret_cast<const float4*>(&Bs[cur][k][tc * 4]);
            *reinterpret_cast<float4*>(&b[4]) =
                *reinterpret_cast<const float4*>(&Bs[cur][k][tc * 4 + 64]);
#pragma unroll
            for (int i = 0; i < 8; ++i)
#pragma unroll
                for (int j = 0; j < 8; ++j)
                    acc[i][j] = fmaf(a[i], b[j], acc[i][j]);
        }

        if (kt < NKT - 1) {
            As[nxt][a_col4 + 0][a_row] = av.x;
            As[nxt][a_col4 + 1][a_row] = av.y;
            As[nxt][a_col4 + 2][a_row] = av.z;
            As[nxt][a_col4 + 3][a_row] = av.w;
            *reinterpret_cast<float4*>(&Bs[nxt][b_krow][b_col4]) = bv;
            __syncthreads();
        }
    }

    // --- fused epilogue: z = beta - sqrt(max(x2 + y2 - 2*cross, 0)) ---
    const float beta_v = __ldg(beta);

    float xr[8], yc[8];
#pragma unroll
    for (int i = 0; i < 8; ++i) {
        int r = (i < 4) ? (tr * 4 + i) : (tr * 4 + 64 + (i - 4));
        xr[i] = g_x2[brow + r];
    }
#pragma unroll
    for (int j = 0; j < 8; ++j) {
        int c = (j < 4) ? (tc * 4 + j) : (tc * 4 + 64 + (j - 4));
        yc[j] = g_y2[bcol + c];
    }

#pragma unroll
    for (int i = 0; i < 8; ++i) {
        int r = (i < 4) ? (tr * 4 + i) : (tr * 4 + 64 + (i - 4));
        float* orow = out + (size_t)(brow + r) * N_COL + bcol;
        float z[8];
#pragma unroll
        for (int j = 0; j < 8; ++j) {
            float d2 = xr[i] + yc[j] - 2.f * acc[i][j];
            d2 = fmaxf(d2, 0.f);
            z[j] = beta_v - sqrtf(d2);
        }
        *reinterpret_cast<float4*>(orow + tc * 4)      = *reinterpret_cast<float4*>(&z[0]);
        *reinterpret_cast<float4*>(orow + tc * 4 + 64) = *reinterpret_cast<float4*>(&z[4]);
    }
}

// ---------------------------------------------------------------------------
extern "C" void kernel_launch(void* const* d_in, const int* in_sizes, int n_in,
                              void* d_out, int out_size) {
    const float* X    = (const float*)d_in[0];  // [8192, 256]
    const float* Y    = (const float*)d_in[1];  // [256, 8192]
    const float* beta = (const float*)d_in[2];  // [1]
    float* out        = (float*)d_out;          // [8192, 8192]

    row_norms_kernel<<<N_ROW / 256, 256>>>(X);
    col_norms_kernel<<<N_COL / 256, 256>>>(Y);

    dim3 grid(N_COL / 128, N_ROW / 128);
    l2_gemm_kernel<<<grid, 256>>>(X, Y, beta, out);
}

// round 6
// speedup vs baseline: 3.9383x; 3.9291x over previous
#include <cuda_runtime.h>
#include <cuda_bf16.h>

#define N_ROW 8192
#define N_COL 8192
#define RANK  256

#define BM 128
#define BN 128
#define BK 32
#define NKT (RANK / BK)   // 8 K-iterations

// ---------------- device scratch (no dynamic allocation allowed) -----------
__device__ float g_x2[N_ROW];
__device__ float g_y2[N_COL];
__device__ __nv_bfloat16 g_Xb[(size_t)N_ROW * RANK];   // bf16 X, row-major [M][K]
__device__ __nv_bfloat16 g_Yb[(size_t)RANK * N_COL];   // bf16 Y, row-major [K][N]

// ---------------- PTX helpers (all baseline sm_80+ features) ---------------
__device__ __forceinline__ unsigned smem_u32(const void* p) {
    unsigned a;
    asm("{ .reg .u64 t; cvta.to.shared.u64 t, %1; cvt.u32.u64 %0, t; }"
        : "=r"(a) : "l"(p));
    return a;
}

#define CP16(dst, src) \
    asm volatile("cp.async.cg.shared.global [%0], [%1], 16;" :: "r"(dst), "l"(src))
#define CPCOMMIT() asm volatile("cp.async.commit_group;" ::: "memory")
#define CPWAIT1()  asm volatile("cp.async.wait_group 1;" ::: "memory")

__device__ __forceinline__ uint4 ldsm4(unsigned a) {
    uint4 r;
    asm volatile("ldmatrix.sync.aligned.m8n8.x4.shared.b16 {%0,%1,%2,%3}, [%4];"
                 : "=r"(r.x), "=r"(r.y), "=r"(r.z), "=r"(r.w) : "r"(a));
    return r;
}
__device__ __forceinline__ uint4 ldsm4t(unsigned a) {
    uint4 r;
    asm volatile("ldmatrix.sync.aligned.m8n8.x4.trans.shared.b16 {%0,%1,%2,%3}, [%4];"
                 : "=r"(r.x), "=r"(r.y), "=r"(r.z), "=r"(r.w) : "r"(a));
    return r;
}
__device__ __forceinline__ void mma16816(float4& c, uint4 a, unsigned b0, unsigned b1) {
    asm volatile(
        "mma.sync.aligned.m16n8k16.row.col.f32.bf16.bf16.f32 "
        "{%0,%1,%2,%3}, {%4,%5,%6,%7}, {%8,%9}, {%0,%1,%2,%3};"
        : "+f"(c.x), "+f"(c.y), "+f"(c.z), "+f"(c.w)
        : "r"(a.x), "r"(a.y), "r"(a.z), "r"(a.w), "r"(b0), "r"(b1));
}

// ---------------- converters (fused with exact fp32 norms) -----------------
// X [8192,256] f32 -> g_Xb bf16 + g_x2 (warp per row)
__global__ void convert_x_kernel(const float* __restrict__ X) {
    const int lane = threadIdx.x & 31;
    const int row  = blockIdx.x * 8 + (threadIdx.x >> 5);
    const float4* p = reinterpret_cast<const float4*>(X + (size_t)row * RANK + lane * 8);
    float4 a = p[0], b = p[1];
    float s = 0.f;
    s = fmaf(a.x, a.x, s); s = fmaf(a.y, a.y, s);
    s = fmaf(a.z, a.z, s); s = fmaf(a.w, a.w, s);
    s = fmaf(b.x, b.x, s); s = fmaf(b.y, b.y, s);
    s = fmaf(b.z, b.z, s); s = fmaf(b.w, b.w, s);

    __nv_bfloat162 h0 = __floats2bfloat162_rn(a.x, a.y);
    __nv_bfloat162 h1 = __floats2bfloat162_rn(a.z, a.w);
    __nv_bfloat162 h2 = __floats2bfloat162_rn(b.x, b.y);
    __nv_bfloat162 h3 = __floats2bfloat162_rn(b.z, b.w);
    uint4 v;
    v.x = *reinterpret_cast<unsigned*>(&h0);
    v.y = *reinterpret_cast<unsigned*>(&h1);
    v.z = *reinterpret_cast<unsigned*>(&h2);
    v.w = *reinterpret_cast<unsigned*>(&h3);
    *reinterpret_cast<uint4*>(g_Xb + (size_t)row * RANK + lane * 8) = v;

#pragma unroll
    for (int o = 16; o > 0; o >>= 1) s += __shfl_xor_sync(0xffffffffu, s, o);
    if (lane == 0) g_x2[row] = s;
}

// Y [256,8192] f32 -> g_Yb bf16 (same layout) + g_y2. Thread = 2 columns.
__global__ void convert_y_kernel(const float* __restrict__ Y) {
    const int j = (blockIdx.x * blockDim.x + threadIdx.x) * 2;
    float s0 = 0.f, s1 = 0.f;
#pragma unroll 8
    for (int k = 0; k < RANK; ++k) {
        float2 v = *reinterpret_cast<const float2*>(Y + (size_t)k * N_COL + j);
        s0 = fmaf(v.x, v.x, s0);
        s1 = fmaf(v.y, v.y, s1);
        __nv_bfloat162 h = __floats2bfloat162_rn(v.x, v.y);
        *reinterpret_cast<__nv_bfloat162*>(g_Yb + (size_t)k * N_COL + j) = h;
    }
    g_y2[j]     = s0;
    g_y2[j + 1] = s1;
}

// ---------------- HMMA GEMM + fused epilogue -------------------------------
// smem swizzles:
//  A tile [128 rows][32 bf16] = 64B rows (4 chunks of 16B):
//    physical chunk = c ^ ((row>>1)&3)  -> conflict-free ldmatrix phases
//  B tile [32 k-rows][128 bf16] = 256B rows (16 chunks):
//    physical chunk = c ^ (row&7)       -> conflict-free ldmatrix.trans phases
// Both swizzle terms are invariant under row+64 (A) / row+16 (B) loader offsets.
__global__ __launch_bounds__(256, 2)
void l2_mma_kernel(const float* __restrict__ beta, float* __restrict__ out) {
    __shared__ __align__(128) char smA[2][BM * 64];    // 2 x 8 KB
    __shared__ __align__(128) char smB[2][BK * 256];   // 2 x 8 KB

    const int tid  = threadIdx.x;
    const int lane = tid & 31;
    const int wid  = tid >> 5;
    const int brow = blockIdx.y * BM;
    const int bcol = blockIdx.x * BN;
    const int wm   = (wid & 1) * 64;   // warp M offset (2 warp-rows)
    const int wn   = (wid >> 1) * 32;  // warp N offset (4 warp-cols)

    const unsigned sA0 = smem_u32(smA[0]), sA1 = smem_u32(smA[1]);
    const unsigned sB0 = smem_u32(smB[0]), sB1 = smem_u32(smB[1]);

    float4 acc[4][4];
#pragma unroll
    for (int i = 0; i < 4; ++i)
#pragma unroll
        for (int j = 0; j < 4; ++j) acc[i][j] = make_float4(0.f, 0.f, 0.f, 0.f);

    // ---- loader assignments (invariant across stages/iters) ----
    const int ar = tid >> 2, ac = tid & 3;          // A: rows ar, ar+64
    const int apc = ac ^ ((ar >> 1) & 3);
    const int br = tid >> 4, bc = tid & 15;         // B: k-rows br, br+16
    const int bpc = bc ^ (br & 7);

    const char* aSrc = (const char*)(g_Xb + (size_t)(brow + ar) * RANK + ac * 8);
    const char* bSrc = (const char*)(g_Yb + (size_t)br * N_COL + bcol + bc * 8);
    const unsigned aDst = ar * 64 + apc * 16;
    const unsigned bDst = br * 256 + bpc * 16;

    // stage-load lambda (4 cp.async x 16B per thread = 16 KB per stage)
    auto load_stage = [&](int buf, int kt) {
        const unsigned sA = buf ? sA1 : sA0;
        const unsigned sB = buf ? sB1 : sB0;
        CP16(sA + aDst,        aSrc + kt * 64);                          // rows 0-63
        CP16(sA + aDst + 4096, aSrc + (size_t)64 * RANK * 2 + kt * 64);  // rows 64-127
        CP16(sB + bDst,        bSrc + (size_t)(kt * BK)      * N_COL * 2);
        CP16(sB + bDst + 4096, bSrc + (size_t)(kt * BK + 16) * N_COL * 2);
    };

    load_stage(0, 0);
    CPCOMMIT();

    const int lr = lane & 15, lc = lane >> 4;

#pragma unroll 1
    for (int kt = 0; kt < NKT; ++kt) {
        if (kt + 1 < NKT) load_stage((kt + 1) & 1, kt + 1);
        CPCOMMIT();               // commit every iter -> wait_group accounting stays fixed
        CPWAIT1();                // stage kt resident
        __syncthreads();

        const unsigned sA = (kt & 1) ? sA1 : sA0;
        const unsigned sB = (kt & 1) ? sB1 : sB0;

#pragma unroll
        for (int k16 = 0; k16 < 2; ++k16) {
            uint4 af[4];
#pragma unroll
            for (int mt = 0; mt < 4; ++mt) {
                int row = wm + mt * 16 + lr;
                int pc  = (k16 * 2 + lc) ^ ((row >> 1) & 3);
                af[mt] = ldsm4(sA + row * 64 + pc * 16);
            }
            uint4 bfr[2];
#pragma unroll
            for (int nt = 0; nt < 2; ++nt) {
                int kr = k16 * 16 + lr;
                int c  = (wn >> 3) + nt * 2 + lc;
                int pc = c ^ (kr & 7);
                bfr[nt] = ldsm4t(sB + kr * 256 + pc * 16);
            }
#pragma unroll
            for (int mt = 0; mt < 4; ++mt) {
                mma16816(acc[mt][0], af[mt], bfr[0].x, bfr[0].y);
                mma16816(acc[mt][1], af[mt], bfr[0].z, bfr[0].w);
                mma16816(acc[mt][2], af[mt], bfr[1].x, bfr[1].y);
                mma16816(acc[mt][3], af[mt], bfr[1].z, bfr[1].w);
            }
        }
        __syncthreads();          // stage kt free for reuse by kt+2 prefetch
    }

    // ---- fused epilogue: z = beta - sqrt(max(x2 + y2 - 2*cross, 0)) ----
    const float beta_v = __ldg(beta);
    const int g = lane >> 2, t = lane & 3;

    float y2v[4][2];
#pragma unroll
    for (int nn = 0; nn < 4; ++nn) {
        float2 y = *reinterpret_cast<const float2*>(g_y2 + bcol + wn + nn * 8 + t * 2);
        y2v[nn][0] = y.x;
        y2v[nn][1] = y.y;
    }

#pragma unroll
    for (int mt = 0; mt < 4; ++mt) {
        const int r0 = brow + wm + mt * 16 + g;
        const float x0 = g_x2[r0];
        const float x1 = g_x2[r0 + 8];
        float* o0 = out + (size_t)r0 * N_COL + bcol + wn;
        float* o1 = o0 + (size_t)8 * N_COL;
#pragma unroll
        for (int nn = 0; nn < 4; ++nn) {
            float4 a = acc[mt][nn];
            float2 z0, z1;
            z0.x = beta_v - sqrtf(fmaxf(fmaf(-2.f, a.x, x0 + y2v[nn][0]), 0.f));
            z0.y = beta_v - sqrtf(fmaxf(fmaf(-2.f, a.y, x0 + y2v[nn][1]), 0.f));
            z1.x = beta_v - sqrtf(fmaxf(fmaf(-2.f, a.z, x1 + y2v[nn][0]), 0.f));
            z1.y = beta_v - sqrtf(fmaxf(fmaf(-2.f, a.w, x1 + y2v[nn][1]), 0.f));
            *reinterpret_cast<float2*>(o0 + nn * 8 + t * 2) = z0;
            *reinterpret_cast<float2*>(o1 + nn * 8 + t * 2) = z1;
        }
    }
}

// ---------------------------------------------------------------------------
extern "C" void kernel_launch(void* const* d_in, const int* in_sizes, int n_in,
                              void* d_out, int out_size) {
    const float* X    = (const float*)d_in[0];  // [8192, 256]
    const float* Y    = (const float*)d_in[1];  // [256, 8192]
    const float* beta = (const float*)d_in[2];  // [1]
    float* out        = (float*)d_out;          // [8192, 8192]

    convert_x_kernel<<<N_ROW / 8, 256>>>(X);
    convert_y_kernel<<<N_COL / 2 / 256, 256>>>(Y);

    dim3 grid(N_COL / BN, N_ROW / BM);          // (64, 64)
    l2_mma_kernel<<<grid, 256>>>(beta, out);
}